// round 3
// baseline (speedup 1.0000x reference)
#include <cuda_runtime.h>
#include <cstdint>

#define T_STEPS 128
#define B_TOT   8192
#define H_DIM   256
#define NTH     256

typedef unsigned long long u64;

// ---- packed f32x2 helpers (Blackwell; ptxas never emits these from C++) ----
__device__ __forceinline__ u64 pk2(float lo, float hi) {
    u64 r; asm("mov.b64 %0, {%1, %2};" : "=l"(r) : "f"(lo), "f"(hi)); return r;
}
__device__ __forceinline__ void unpk2(u64 v, float& lo, float& hi) {
    asm("mov.b64 {%0, %1}, %2;" : "=f"(lo), "=f"(hi) : "l"(v));
}
__device__ __forceinline__ u64 fma2(u64 a, u64 b, u64 c) {
    u64 d; asm("fma.rn.f32x2 %0, %1, %2, %3;" : "=l"(d) : "l"(a), "l"(b), "l"(c)); return d;
}
__device__ __forceinline__ u64 mul2(u64 a, u64 b) {
    u64 d; asm("mul.rn.f32x2 %0, %1, %2;" : "=l"(d) : "l"(a), "l"(b)); return d;
}
__device__ __forceinline__ u64 add2(u64 a, u64 b) {
    u64 d; asm("add.rn.f32x2 %0, %1, %2;" : "=l"(d) : "l"(a), "l"(b)); return d;
}
// per-half: (m > 1.0f) ? 1.0f : 0.0f
__device__ __forceinline__ u64 gt1_2(u64 m) {
    u64 r;
    asm("{\n\t"
        ".reg .f32 plo, phi, rl, rh;\n\t"
        "mov.b64 {plo, phi}, %1;\n\t"
        "set.gt.f32.f32 rl, plo, 0f3F800000;\n\t"
        "set.gt.f32.f32 rh, phi, 0f3F800000;\n\t"
        "mov.b64 %0, {rl, rh};\n\t"
        "}" : "=l"(r) : "l"(m));
    return r;
}

// Mapping: lane = batch (32 b per warp), registers = 4 h per thread (2 packed pairs).
// Block = 8 warps -> 32 b x 32 h. Grid = 256 b-tiles x 8 h-slices = 2048 blocks.
// x staged in two 64-step chunks (16KB smem) -> 7 blocks/SM -> ~2.0 balanced waves.
__global__ void __launch_bounds__(NTH, 7)
snn_fused_kernel(const float2* __restrict__ x2,   // [T, B] pairs (x0, x1)
                 const float4* __restrict__ w14,  // [H/2] quads {w0[h],w1[h],w0[h+1],w1[h+1]}
                 const float*  __restrict__ w2,   // [2, 256]
                 float* __restrict__ out)         // [B, 2] (pre-zeroed)
{
    __shared__ __align__(16) float2 sx[64][32];   // 16KB, one chunk of 64 steps
    __shared__ float ps[8][32][2];                // per-warp partials (2KB)

    const int tid  = threadIdx.x;
    const int lane = tid & 31, wrp = tid >> 5;
    const int hs   = blockIdx.x & 7;              // h-slice (low bits -> co-resident blocks share b-tile in L2)
    const int b0   = (blockIdx.x >> 3) * 32;      // b-tile
    const int h0   = hs * 32 + wrp * 4;           // this thread's first h

    // W1 pairs for h0..h0+3
    const float4 qa = w14[(h0 >> 1) + 0];
    const float4 qb = w14[(h0 >> 1) + 1];
    const u64 w0p0 = pk2(qa.x, qa.z), w1p0 = pk2(qa.y, qa.w);
    const u64 w0p1 = pk2(qb.x, qb.z), w1p1 = pk2(qb.y, qb.w);

    const u64 BETA2 = 0x3F6666663F666666ULL;  // (0.9f, 0.9f)
    const u64 NEG12 = 0xBF800000BF800000ULL;  // (-1.0f, -1.0f)

    u64 m0 = 0, m1 = 0;        // mem pairs
    u64 r0 = 0, r1 = 0;        // reset (prev spike) pairs, float 0/1

    // ---------------- chunk 0: t in [0,64) ----------------
    #pragma unroll
    for (int k = 0; k < 8; ++k) {
        int idx = tid + k * NTH;
        int t = idx >> 5, b = idx & 31;
        sx[t][b] = x2[(size_t)t * B_TOT + b0 + b];
    }
    __syncthreads();

    #pragma unroll 4
    for (int t = 0; t < 64; ++t) {
        float2 xv = sx[t][lane];
        u64 x0d = pk2(xv.x, xv.x);
        u64 x1d = pk2(xv.y, xv.y);
        u64 c0 = fma2(x0d, w0p0, mul2(x1d, w1p0));
        u64 c1 = fma2(x0d, w0p1, mul2(x1d, w1p1));
        m0 = fma2(m0, BETA2, c0);  m1 = fma2(m1, BETA2, c1);
        m0 = fma2(r0, NEG12, m0);  m1 = fma2(r1, NEG12, m1);
        r0 = gt1_2(m0);            r1 = gt1_2(m1);
    }
    __syncthreads();   // all warps done with chunk 0 before overwrite

    // ---------------- chunk 1: t in [64,128) ----------------
    #pragma unroll
    for (int k = 0; k < 8; ++k) {
        int idx = tid + k * NTH;
        int t = idx >> 5, b = idx & 31;
        sx[t][b] = x2[(size_t)(64 + t) * B_TOT + b0 + b];
    }
    __syncthreads();

    #pragma unroll 3
    for (int t = 0; t < 54; ++t) {   // global t = 64..117
        float2 xv = sx[t][lane];
        u64 x0d = pk2(xv.x, xv.x);
        u64 x1d = pk2(xv.y, xv.y);
        u64 c0 = fma2(x0d, w0p0, mul2(x1d, w1p0));
        u64 c1 = fma2(x0d, w0p1, mul2(x1d, w1p1));
        m0 = fma2(m0, BETA2, c0);  m1 = fma2(m1, BETA2, c1);
        m0 = fma2(r0, NEG12, m0);  m1 = fma2(r1, NEG12, m1);
        r0 = gt1_2(m0);            r1 = gt1_2(m1);
    }

    u64 cnt0 = 0, cnt1 = 0;
    #pragma unroll
    for (int t = 54; t < 64; ++t) {  // global t = 118..127: count spikes
        float2 xv = sx[t][lane];
        u64 x0d = pk2(xv.x, xv.x);
        u64 x1d = pk2(xv.y, xv.y);
        u64 c0 = fma2(x0d, w0p0, mul2(x1d, w1p0));
        u64 c1 = fma2(x0d, w0p1, mul2(x1d, w1p1));
        m0 = fma2(m0, BETA2, c0);  m1 = fma2(m1, BETA2, c1);
        m0 = fma2(r0, NEG12, m0);  m1 = fma2(r1, NEG12, m1);
        r0 = gt1_2(m0);            r1 = gt1_2(m1);
        cnt0 = add2(cnt0, r0);     cnt1 = add2(cnt1, r1);
    }

    // ---------------- epilogue: partial dot with W2 over this thread's 4 h ----------------
    float c00, c01, c10, c11;
    unpk2(cnt0, c00, c01);
    unpk2(cnt1, c10, c11);
    float s0 = c00 * __ldg(&w2[h0])         + c01 * __ldg(&w2[h0 + 1])
             + c10 * __ldg(&w2[h0 + 2])     + c11 * __ldg(&w2[h0 + 3]);
    float s1 = c00 * __ldg(&w2[H_DIM + h0])     + c01 * __ldg(&w2[H_DIM + h0 + 1])
             + c10 * __ldg(&w2[H_DIM + h0 + 2]) + c11 * __ldg(&w2[H_DIM + h0 + 3]);
    ps[wrp][lane][0] = s0;
    ps[wrp][lane][1] = s1;
    __syncthreads();

    if (wrp < 2) {            // warp 0 -> o=0, warp 1 -> o=1
        const int o = wrp;
        float s = 0.f;
        #pragma unroll
        for (int w = 0; w < 8; ++w) s += ps[w][lane][o];
        atomicAdd(&out[(b0 + lane) * 2 + o], 0.1f * s);
    }
}

__global__ void zero_out_kernel(float* __restrict__ out) {
    out[blockIdx.x * NTH + threadIdx.x] = 0.f;
}

extern "C" void kernel_launch(void* const* d_in, const int* in_sizes, int n_in,
                              void* d_out, int out_size) {
    const float2* x  = (const float2*)d_in[0];   // [128, 8192, 2] f32
    const float4* W1 = (const float4*)d_in[1];   // [256, 2] f32
    const float*  W2 = (const float*)d_in[2];    // [2, 256] f32
    float* out = (float*)d_out;                  // [8192, 2] f32
    zero_out_kernel<<<(B_TOT * 2) / NTH, NTH>>>(out);
    snn_fused_kernel<<<(B_TOT / 32) * 8, NTH>>>(x, W1, W2, out);
}